// round 8
// baseline (speedup 1.0000x reference)
#include <cuda_runtime.h>
#include <math.h>

#define N_NODES 50000
#define E_EDGES 1600000
#define HC      32
#define G_GRAPHS 512
#define STRIDE  96          // padded CSR bucket; indeg ~ Poisson(32), P(>=96) ~ e^-40

typedef unsigned long long u64;

// ---------------- static scratch ----------------
__device__ int   g_cnt   [N_NODES];          // in-degree == bucket fill count
__device__ int   g_outdeg[N_NODES];
__device__ int   g_col   [N_NODES * STRIDE]; // padded buckets of source ROW OFFSETS (s*HC)
__device__ float g_xl [N_NODES * HC];
__device__ float g_xr [N_NODES * HC];
__device__ float g_xl2[N_NODES * HC];
__device__ float g_xr2[N_NODES * HC];
__device__ float g_sums[G_GRAPHS * HC];

// ---------------- packed f32x2 helpers (sm_103a) ----------------
__device__ __forceinline__ u64 add2(u64 a, u64 b) {
    u64 r; asm("add.rn.f32x2 %0, %1, %2;" : "=l"(r) : "l"(a), "l"(b)); return r;
}
__device__ __forceinline__ u64 fma2(u64 a, u64 b, u64 c) {
    u64 r; asm("fma.rn.f32x2 %0, %1, %2, %3;" : "=l"(r) : "l"(a), "l"(b), "l"(c)); return r;
}
__device__ __forceinline__ u64 abs2(u64 a) { return a & 0x7fffffff7fffffffULL; }
__device__ __forceinline__ u64 pk(float lo, float hi) {
    u64 r; asm("mov.b64 %0, {%1, %2};" : "=l"(r) : "f"(lo), "f"(hi)); return r;
}
__device__ __forceinline__ void unpk(u64 a, float& lo, float& hi) {
    asm("mov.b64 {%0, %1}, %2;" : "=f"(lo), "=f"(hi) : "l"(a));
}
__device__ __forceinline__ float ex2(float x) {
    float r; asm("ex2.approx.f32 %0, %1;" : "=f"(r) : "f"(x)); return r;
}

// ---------------- kernels ----------------
__global__ void zero_kernel() {
    int i = blockIdx.x * blockDim.x + threadIdx.x;
    if (i < N_NODES) { g_cnt[i] = 0; g_outdeg[i] = 0; }
    if (i < G_GRAPHS * HC) g_sums[i] = 0.f;
}

// fused CSR build: bucket scatter (pos atomic == indeg count) + outdeg; 4 edges/thread.
// Stores s*HC (row offset) so conv kernels skip the multiply.
__global__ void build_kernel(const int* __restrict__ ei) {
    int e0 = (blockIdx.x * blockDim.x + threadIdx.x) * 4;
    if (e0 >= E_EDGES) return;
    int4 s = *(const int4*)(ei + e0);
    int4 d = *(const int4*)(ei + E_EDGES + e0);
    int p0 = atomicAdd(&g_cnt[d.x], 1);
    int p1 = atomicAdd(&g_cnt[d.y], 1);
    int p2 = atomicAdd(&g_cnt[d.z], 1);
    int p3 = atomicAdd(&g_cnt[d.w], 1);
    g_col[d.x * STRIDE + p0] = s.x * HC;
    g_col[d.y * STRIDE + p1] = s.y * HC;
    g_col[d.z * STRIDE + p2] = s.z * HC;
    g_col[d.w * STRIDE + p3] = s.w * HC;
    atomicAdd(&g_outdeg[s.x], 1); atomicAdd(&g_outdeg[s.y], 1);
    atomicAdd(&g_outdeg[s.z], 1); atomicAdd(&g_outdeg[s.w], 1);
}

// x0 = [1, deg, rand]; xl/xr = x0 @ W^T + b. warp per node, lane = out channel
__global__ void feat_lin1_kernel(const float* __restrict__ rand_feat,
                                 const float* __restrict__ Wl, const float* __restrict__ bl,
                                 const float* __restrict__ Wr, const float* __restrict__ br) {
    int idx = blockIdx.x * blockDim.x + threadIdx.x;
    int node = idx >> 5, lane = idx & 31;
    if (node >= N_NODES) return;
    float x1 = (float)(g_outdeg[node] + g_cnt[node]);
    float x2 = rand_feat[node];
    g_xl[idx] = Wl[lane * 3 + 0] + Wl[lane * 3 + 1] * x1 + Wl[lane * 3 + 2] * x2 + bl[lane];
    g_xr[idx] = Wr[lane * 3 + 0] + Wr[lane * 3 + 1] * x1 + Wr[lane * 3 + 2] * x2 + br[lane];
}

// GATv2 conv: warp per destination node, 4 edge-subgroups of 8 lanes,
// lane holds 4 channels -> 128B row in ONE LDG.128, arithmetic in packed f32x2.
// LeakyReLU(m)*att*log2e = a06*m + a04*|m|; Sum(a06*xr) hoisted; -pself folded
// into the score seed so w = ex2(p) directly.
// Per-head score reduce = shfl xor 1,2. Cross-subgroup combine = shfl xor 8,16.
// MODE 0: reads g_xl/g_xr, fused 32->32 x2 linear (smem transpose, FFMA2) -> g_xl2/g_xr2.
// MODE 1: reads g_xl2/g_xr2, fused mean-pool atomicAdd into g_sums.
template<int MODE>
__global__ void __launch_bounds__(256, 5)
conv_kernel(const float* __restrict__ att, const float* __restrict__ bias,
            const float* __restrict__ Wl, const float* __restrict__ bl,
            const float* __restrict__ Wr, const float* __restrict__ br,
            const int* __restrict__ batch) {
    const float* __restrict__ xl = (MODE == 0) ? g_xl : g_xl2;
    const float* __restrict__ xr = (MODE == 0) ? g_xr : g_xr2;
    const unsigned FULL = 0xffffffffu;

    __shared__ float sWl[32 * 36];
    __shared__ float sWr[32 * 36];
    __shared__ float so [8 * 32];
    if (MODE == 0) {
        for (int i = threadIdx.x; i < 1024; i += blockDim.x) {
            int r = i >> 5, c = i & 31;
            sWl[r * 36 + c] = Wl[i];
            sWr[r * 36 + c] = Wr[i];
        }
        __syncthreads();
    }
    int gidx = blockIdx.x * blockDim.x + threadIdx.x;
    int node = gidx >> 5, lane = gidx & 31;
    if (node >= N_NODES) return;
    const int sub = lane >> 3;     // edge slot 0..3
    const int q   = lane & 7;      // channel quad 0..7
    const int wlocal = (threadIdx.x >> 5);
    const int nodeHC = node * HC;

    const float LOG2E = 1.4426950408889634f;
    const float4 attr = *(const float4*)(att + q * 4);
    const u64 a06p0 = pk(0.6f * LOG2E * attr.x, 0.6f * LOG2E * attr.y);
    const u64 a06p1 = pk(0.6f * LOG2E * attr.z, 0.6f * LOG2E * attr.w);
    const u64 a04p0 = pk(0.4f * LOG2E * attr.x, 0.4f * LOG2E * attr.y);
    const u64 a04p1 = pk(0.4f * LOG2E * attr.z, 0.4f * LOG2E * attr.w);

    const ulonglong2 xrp = *(const ulonglong2*)(xr + nodeHC + q * 4);

    // hoisted per-node term: sum_c a06_c * xr_c (this lane's 4 channels)
    u64 bp = fma2(a06p0, xrp.x, pk(0.f, 0.f));
    bp = fma2(a06p1, xrp.y, bp);
    float blo, bhi; unpk(bp, blo, bhi);
    const float base = blo + bhi;

    // self loop + softmax baseline pself (log2-scaled, per head)
    const ulonglong2 vsp = *(const ulonglong2*)(xl + nodeHC + q * 4);
    u64 pp = fma2(a06p0, vsp.x, pk(base, 0.f));
    pp = fma2(a06p1, vsp.y, pp);
    pp = fma2(a04p0, abs2(add2(vsp.x, xrp.x)), pp);
    pp = fma2(a04p1, abs2(add2(vsp.y, xrp.y)), pp);
    float plo, phi; unpk(pp, plo, phi);
    float ps = plo + phi;
    ps += __shfl_xor_sync(FULL, ps, 1);
    ps += __shfl_xor_sync(FULL, ps, 2);
    // fold base and -pself/4 into the per-edge score seed
    const u64 seed2 = pk(base - 0.25f * ps, 0.f);

    float wsf = (sub == 0) ? 1.f : 0.f;   // self weight: ex2(ps - ps) = 1
    float denom = wsf;
    u64 wsp = pk(wsf, wsf);
    u64 acc0 = fma2(wsp, vsp.x, pk(0.f, 0.f));
    u64 acc1 = fma2(wsp, vsp.y, pk(0.f, 0.f));

    const int beg = node * STRIDE;
    const int end = beg + g_cnt[node];

    int c0 = (beg + sub     < end) ? __ldg(g_col + beg + sub)     : nodeHC;
    int c1 = (beg + 4 + sub < end) ? __ldg(g_col + beg + 4 + sub) : nodeHC;

    for (int e = beg; e < end; e += 8) {
        bool ok0 = (e + sub)     < end;
        bool ok1 = (e + 4 + sub) < end;
        int s0 = c0, s1 = c1;
        int n0 = e + 8 + sub, n1 = e + 12 + sub;
        c0 = (n0 < end) ? __ldg(g_col + n0) : nodeHC;
        c1 = (n1 < end) ? __ldg(g_col + n1) : nodeHC;

        const ulonglong2 A = *(const ulonglong2*)(xl + s0 + q * 4);
        const ulonglong2 B = *(const ulonglong2*)(xl + s1 + q * 4);

        u64 p0p = fma2(a06p0, A.x, seed2);
        p0p = fma2(a06p1, A.y, p0p);
        p0p = fma2(a04p0, abs2(add2(A.x, xrp.x)), p0p);
        p0p = fma2(a04p1, abs2(add2(A.y, xrp.y)), p0p);
        u64 p1p = fma2(a06p0, B.x, seed2);
        p1p = fma2(a06p1, B.y, p1p);
        p1p = fma2(a04p0, abs2(add2(B.x, xrp.x)), p1p);
        p1p = fma2(a04p1, abs2(add2(B.y, xrp.y)), p1p);

        float l0, h0, l1, h1;
        unpk(p0p, l0, h0);
        unpk(p1p, l1, h1);
        float p0 = l0 + h0;
        float p1 = l1 + h1;
        p0 += __shfl_xor_sync(FULL, p0, 1);
        p0 += __shfl_xor_sync(FULL, p0, 2);
        p1 += __shfl_xor_sync(FULL, p1, 1);
        p1 += __shfl_xor_sync(FULL, p1, 2);
        float w0 = ok0 ? ex2(p0) : 0.f;
        float w1 = ok1 ? ex2(p1) : 0.f;
        denom += w0 + w1;
        u64 w0p = pk(w0, w0);
        u64 w1p = pk(w1, w1);
        acc0 = fma2(w0p, A.x, acc0);
        acc1 = fma2(w0p, A.y, acc1);
        acc0 = fma2(w1p, B.x, acc0);
        acc1 = fma2(w1p, B.y, acc1);
    }

    // unpack accumulators, combine the 4 edge subgroups (q invariant -> head-safe)
    float4 acc;
    unpk(acc0, acc.x, acc.y);
    unpk(acc1, acc.z, acc.w);
#pragma unroll
    for (int off = 8; off <= 16; off <<= 1) {
        acc.x += __shfl_xor_sync(FULL, acc.x, off);
        acc.y += __shfl_xor_sync(FULL, acc.y, off);
        acc.z += __shfl_xor_sync(FULL, acc.z, off);
        acc.w += __shfl_xor_sync(FULL, acc.w, off);
        denom += __shfl_xor_sync(FULL, denom, off);
    }

    const float4 b4 = *(const float4*)(bias + q * 4);
    float rd = __fdividef(1.f, denom + 1e-16f);
    float4 o4;
    o4.x = fmaf(acc.x, rd, b4.x);
    o4.y = fmaf(acc.y, rd, b4.y);
    o4.z = fmaf(acc.z, rd, b4.z);
    o4.w = fmaf(acc.w, rd, b4.w);
    o4.x = o4.x > 0.f ? o4.x : (__expf(o4.x) - 1.f);
    o4.y = o4.y > 0.f ? o4.y : (__expf(o4.y) - 1.f);
    o4.z = o4.z > 0.f ? o4.z : (__expf(o4.z) - 1.f);
    o4.w = o4.w > 0.f ? o4.w : (__expf(o4.w) - 1.f);

    if (MODE == 0) {
        // fused lin2 via warp-private smem transpose, FFMA2 inner product
        if (sub == 0) *(float4*)&so[wlocal * 32 + q * 4] = o4;
        __syncwarp(FULL);
        u64 aLp = pk(bl[lane], 0.f);
        u64 aRp = pk(br[lane], 0.f);
#pragma unroll
        for (int ch = 0; ch < 8; ch++) {
            const ulonglong2 ov = *(const ulonglong2*)&so[wlocal * 32 + ch * 4];   // broadcast
            const ulonglong2 wl = *(const ulonglong2*)&sWl[lane * 36 + ch * 4];    // conflict-free
            const ulonglong2 wr = *(const ulonglong2*)&sWr[lane * 36 + ch * 4];
            aLp = fma2(ov.x, wl.x, aLp);
            aLp = fma2(ov.y, wl.y, aLp);
            aRp = fma2(ov.x, wr.x, aRp);
            aRp = fma2(ov.y, wr.y, aRp);
        }
        float allo, alhi, arlo, arhi;
        unpk(aLp, allo, alhi);
        unpk(aRp, arlo, arhi);
        g_xl2[nodeHC + lane] = allo + alhi;
        g_xr2[nodeHC + lane] = arlo + arhi;
    } else {
        if (sub == 0) {
            int g = batch[node];
            float* dst = &g_sums[g * HC + q * 4];
            atomicAdd(dst + 0, o4.x);
            atomicAdd(dst + 1, o4.y);
            atomicAdd(dst + 2, o4.z);
            atomicAdd(dst + 3, o4.w);
        }
    }
}

__device__ __forceinline__ int lbound(const int* __restrict__ a, int key) {
    int lo = 0, hi = N_NODES;
    while (lo < hi) {
        int mid = (lo + hi) >> 1;
        if (a[mid] < key) lo = mid + 1; else hi = mid;
    }
    return lo;
}

// one warp per graph: counts via binary search on sorted batch, mean pool, fc, log_softmax
__global__ void head_kernel(const int* __restrict__ batch,
                            const float* __restrict__ Wfc, const float* __restrict__ bfc,
                            float* __restrict__ out) {
    int g = blockIdx.x;
    int lane = threadIdx.x;
    int lo = lbound(batch, g);
    int hi = lbound(batch, g + 1);
    float cnt = fmaxf((float)(hi - lo), 1.f);
    float pooled = g_sums[g * HC + lane] / cnt;
    float p0 = pooled * Wfc[lane];
    float p1 = pooled * Wfc[HC + lane];
#pragma unroll
    for (int off = 16; off; off >>= 1) {
        p0 += __shfl_xor_sync(0xffffffffu, p0, off);
        p1 += __shfl_xor_sync(0xffffffffu, p1, off);
    }
    if (lane == 0) {
        float l0 = p0 + bfc[0];
        float l1 = p1 + bfc[1];
        float mx = fmaxf(l0, l1);
        float lse = mx + logf(expf(l0 - mx) + expf(l1 - mx));
        out[g * 2 + 0] = l0 - lse;
        out[g * 2 + 1] = l1 - lse;
    }
}

// ---------------- launch ----------------
extern "C" void kernel_launch(void* const* d_in, const int* in_sizes, int n_in,
                              void* d_out, int out_size) {
    const int*   ei        = (const int*)  d_in[0];
    const int*   batch     = (const int*)  d_in[1];
    const float* rand_feat = (const float*)d_in[2];
    const float* W1l  = (const float*)d_in[3];
    const float* b1l  = (const float*)d_in[4];
    const float* W1r  = (const float*)d_in[5];
    const float* b1r  = (const float*)d_in[6];
    const float* att1 = (const float*)d_in[7];
    const float* bias1= (const float*)d_in[8];
    const float* W2l  = (const float*)d_in[9];
    const float* b2l  = (const float*)d_in[10];
    const float* W2r  = (const float*)d_in[11];
    const float* b2r  = (const float*)d_in[12];
    const float* att2 = (const float*)d_in[13];
    const float* bias2= (const float*)d_in[14];
    const float* Wfc  = (const float*)d_in[15];
    const float* bfc  = (const float*)d_in[16];
    float* out = (float*)d_out;

    zero_kernel <<<(N_NODES + 255) / 256, 256>>>();
    build_kernel<<<(E_EDGES / 4 + 255) / 256, 256>>>(ei);

    feat_lin1_kernel<<<(N_NODES * HC + 255) / 256, 256>>>(rand_feat, W1l, b1l, W1r, b1r);

    conv_kernel<0><<<(N_NODES * HC + 255) / 256, 256>>>(
        att1, bias1, W2l, b2l, W2r, b2r, nullptr);
    conv_kernel<1><<<(N_NODES * HC + 255) / 256, 256>>>(
        att2, bias2, nullptr, nullptr, nullptr, nullptr, batch);

    head_kernel<<<G_GRAPHS, 32>>>(batch, Wfc, bfc, out);
}